// round 3
// baseline (speedup 1.0000x reference)
#include <cuda_runtime.h>
#include <cuda_bf16.h>
#include <cstdint>

// ---------------- problem constants ----------------
#define B_SZ 512
#define T_SZ 196
#define D_SZ 256
#define NCHUNK 9
#define TPC 22          // tokens per chunk (last chunk = 20)

// ---------------- device scratch ----------------
__device__ __align__(256) __nv_bfloat16 g_tbf[(size_t)T_SZ * B_SZ * D_SZ]; // [t][b][d], normalized
__device__ __align__(256) __nv_bfloat16 g_vbf[(size_t)T_SZ * B_SZ * D_SZ];
__device__ float g_s[(size_t)NCHUNK * B_SZ * B_SZ];   // partial sum exp(cos)
__device__ float g_w[(size_t)NCHUNK * B_SZ * B_SZ];   // partial sum cos*exp(cos)
__device__ float g_logits[B_SZ * B_SZ];
__device__ float g_part[B_SZ];

// ---------------- PTX helpers (sm_80-class only; NO 'a'-gated features) ----------------
__device__ __forceinline__ uint32_t smem_u32(const void* p) {
    uint32_t a;
    asm("{ .reg .u64 t; cvta.to.shared.u64 t, %1; cvt.u32.u64 %0, t; }" : "=r"(a) : "l"(p));
    return a;
}
__device__ __forceinline__ void cp_async16(uint32_t dst, const void* src) {
    asm volatile("cp.async.cg.shared.global [%0], [%1], 16;" :: "r"(dst), "l"(src) : "memory");
}
__device__ __forceinline__ void cp_commit() {
    asm volatile("cp.async.commit_group;" ::: "memory");
}
template <int N>
__device__ __forceinline__ void cp_wait() {
    asm volatile("cp.async.wait_group %0;" :: "n"(N) : "memory");
}
__device__ __forceinline__ void ldsm_x4(uint32_t (&r)[4], uint32_t addr) {
    asm volatile("ldmatrix.sync.aligned.m8n8.x4.shared.b16 {%0,%1,%2,%3}, [%4];"
                 : "=r"(r[0]), "=r"(r[1]), "=r"(r[2]), "=r"(r[3]) : "r"(addr));
}
__device__ __forceinline__ void mma_16816(float (&d)[4], const uint32_t (&a)[4],
                                          uint32_t b0, uint32_t b1) {
    asm volatile(
        "mma.sync.aligned.m16n8k16.row.col.f32.bf16.bf16.f32 "
        "{%0,%1,%2,%3}, {%4,%5,%6,%7}, {%8,%9}, {%0,%1,%2,%3};"
        : "+f"(d[0]), "+f"(d[1]), "+f"(d[2]), "+f"(d[3])
        : "r"(a[0]), "r"(a[1]), "r"(a[2]), "r"(a[3]), "r"(b0), "r"(b1));
}

// degree-7 Taylor exp on [-1,1] (abs err ~2.5e-5) — avoids MUFU entirely
__device__ __forceinline__ float exp_poly(float x) {
    float p = 1.9841270e-4f;           // 1/5040
    p = fmaf(p, x, 1.3888889e-3f);     // 1/720
    p = fmaf(p, x, 8.3333333e-3f);     // 1/120
    p = fmaf(p, x, 4.1666667e-2f);     // 1/24
    p = fmaf(p, x, 1.6666667e-1f);     // 1/6
    p = fmaf(p, x, 0.5f);
    p = fmaf(p, x, 1.0f);
    p = fmaf(p, x, 1.0f);
    return p;
}

// ---------------- kernel 1: normalize + fp32->bf16 + transpose to [t][b][d] ----------------
__global__ void __launch_bounds__(256) convert_kernel(const float* __restrict__ text,
                                                      const float* __restrict__ vis) {
    const int gw = (blockIdx.x * blockDim.x + threadIdx.x) >> 5;
    const int lane = threadIdx.x & 31;
    const int ROWS = B_SZ * T_SZ;
    const int which = (gw >= ROWS) ? 1 : 0;
    const int r = gw - which * ROWS;
    const int b = r / T_SZ;
    const int t = r - b * T_SZ;

    const float4* src = (const float4*)((which ? vis : text) + ((size_t)b * T_SZ + t) * D_SZ);
    float4 x = src[lane];
    float4 y = src[lane + 32];
    float ss = x.x * x.x + x.y * x.y + x.z * x.z + x.w * x.w
             + y.x * y.x + y.y * y.y + y.z * y.z + y.w * y.w;
#pragma unroll
    for (int o = 16; o; o >>= 1) ss += __shfl_xor_sync(0xffffffffu, ss, o);
    const float rn = rsqrtf(ss);

    __nv_bfloat16* dst = (which ? g_vbf : g_tbf) + ((size_t)t * B_SZ + b) * D_SZ;
    __nv_bfloat162 h0 = __float22bfloat162_rn(make_float2(x.x * rn, x.y * rn));
    __nv_bfloat162 h1 = __float22bfloat162_rn(make_float2(x.z * rn, x.w * rn));
    __nv_bfloat162 h2 = __float22bfloat162_rn(make_float2(y.x * rn, y.y * rn));
    __nv_bfloat162 h3 = __float22bfloat162_rn(make_float2(y.z * rn, y.w * rn));
    uint2 p0, p1;
    p0.x = *(uint32_t*)&h0; p0.y = *(uint32_t*)&h1;
    p1.x = *(uint32_t*)&h2; p1.y = *(uint32_t*)&h3;
    ((uint2*)dst)[lane] = p0;
    ((uint2*)(dst + 128))[lane] = p1;
}

// ---------------- kernel 2: fused per-token GEMM + softmax-pool partials ----------------
// CTA tile: 128 (b) x 128 (c); K = 256 in 4 blocks of 64. 512 threads = 16 warps,
// each warp owns a 32x32 output tile (wm = wid&3 rows, wn = wid>>2 cols).
// Classic multi-stage cp.async pipeline; all warps load and compute.
static constexpr int STAGES = 5;
static constexpr int SLOT_BYTES = 32768;   // A 16KB + B 16KB (one K-block of 64)
static constexpr int A_HALF = 16384;
static constexpr int SMEM_TOTAL = STAGES * SLOT_BYTES;  // 163840

__global__ void __launch_bounds__(512, 1) gemm_pool_kernel() {
    extern __shared__ __align__(1024) char smem[];
    const uint32_t sb = smem_u32(smem);
    const int tid = threadIdx.x;
    const int wid = tid >> 5;
    const int lane = tid & 31;

    const int bx = blockIdx.x;
    const int ch = blockIdx.y;
    const int b0 = (bx & 3) * 128;
    const int c0 = (bx >> 2) * 128;
    const int t0 = ch * TPC;
    const int ntok = min(TPC, T_SZ - t0);
    const int NS = ntok * 4;

    // -------- per-thread producer addressing (4 x 16B chunks per thread per stage) --------
    // q in [0,2048): isB = q>>10, row = (q&1023)>>3, c8 = q&7; swizzled 128B rows.
    uint32_t pdst[4];
    const __nv_bfloat16* psrcbase[4];
    uint32_t psrcrowoff[4];
#pragma unroll
    for (int i = 0; i < 4; ++i) {
        const int q = tid + i * 512;
        const int isB = q >> 10;
        const int q2 = q & 1023;
        const int row = q2 >> 3;
        const int c8 = q2 & 7;
        pdst[i] = (uint32_t)(isB ? A_HALF : 0) + (uint32_t)row * 128
                + ((uint32_t)(c8 ^ (row & 7)) << 4);
        psrcbase[i] = (isB ? g_vbf : g_tbf);
        psrcrowoff[i] = (uint32_t)((isB ? c0 : b0) + row) * D_SZ + (uint32_t)c8 * 8;
    }

    // -------- per-thread MMA fragment addressing --------
    const int wm = wid & 3;
    const int wn = wid >> 2;
    const uint32_t lx = lane & 7;
    const uint32_t aoff = (uint32_t)(wm * 32 + (lane & 15)) * 128;      // A row byte offset
    const uint32_t halfA = (uint32_t)(lane >> 4);
    const uint32_t boff = (uint32_t)(wn * 32 + (lane & 7) + ((lane >> 4) * 8)) * 128;
    const uint32_t halfB = (uint32_t)((lane >> 3) & 1);

    float acc[2][4][4];
    float sac[2][4][4];
    float wac[2][4][4];
#pragma unroll
    for (int mt = 0; mt < 2; ++mt)
#pragma unroll
        for (int nt = 0; nt < 4; ++nt)
#pragma unroll
            for (int r = 0; r < 4; ++r) {
                acc[mt][nt][r] = 0.f; sac[mt][nt][r] = 0.f; wac[mt][nt][r] = 0.f;
            }

    // -------- pipeline --------
    auto load_stage = [&](int s) {
        const int slot = s % STAGES;
        const int t = t0 + (s >> 2);
        const int kb = s & 3;
        const uint32_t sbase = sb + (uint32_t)slot * SLOT_BYTES;
        const size_t toff = (size_t)t * (B_SZ * D_SZ) + (size_t)kb * 64;
#pragma unroll
        for (int i = 0; i < 4; ++i)
            cp_async16(sbase + pdst[i], psrcbase[i] + toff + psrcrowoff[i]);
    };

#pragma unroll
    for (int s = 0; s < STAGES - 1; ++s) { load_stage(s); cp_commit(); }

    for (int s = 0; s < NS; ++s) {
        if (s + STAGES - 1 < NS) load_stage(s + STAGES - 1);
        cp_commit();
        cp_wait<STAGES - 2>();
        __syncthreads();

        const int slot = s % STAGES;
        const uint32_t ab = sb + (uint32_t)slot * SLOT_BYTES;
        const uint32_t bb = ab + A_HALF;
#pragma unroll
        for (int ks = 0; ks < 4; ++ks) {
            const uint32_t ca = (((uint32_t)(ks << 1) | halfA) ^ lx) << 4;
            const uint32_t cb = (((uint32_t)(ks << 1) | halfB) ^ lx) << 4;
            uint32_t a0[4], a1[4], bA[4], bB[4];
            ldsm_x4(a0, ab + aoff + ca);
            ldsm_x4(a1, ab + aoff + 2048 + ca);
            ldsm_x4(bA, bb + boff + cb);
            ldsm_x4(bB, bb + boff + 2048 + cb);
            mma_16816(acc[0][0], a0, bA[0], bA[1]);
            mma_16816(acc[0][1], a0, bA[2], bA[3]);
            mma_16816(acc[0][2], a0, bB[0], bB[1]);
            mma_16816(acc[0][3], a0, bB[2], bB[3]);
            mma_16816(acc[1][0], a1, bA[0], bA[1]);
            mma_16816(acc[1][1], a1, bA[2], bA[3]);
            mma_16816(acc[1][2], a1, bB[0], bB[1]);
            mma_16816(acc[1][3], a1, bB[2], bB[3]);
        }

        if ((s & 3) == 3) {
            // end of a token: fold cos values into softmax-pool partials
#pragma unroll
            for (int mt = 0; mt < 2; ++mt)
#pragma unroll
                for (int nt = 0; nt < 4; ++nt)
#pragma unroll
                    for (int r = 0; r < 4; ++r) {
                        const float c = acc[mt][nt][r];
                        const float e = exp_poly(c);
                        sac[mt][nt][r] += e;
                        wac[mt][nt][r] = fmaf(c, e, wac[mt][nt][r]);
                        acc[mt][nt][r] = 0.f;
                    }
        }
        __syncthreads();
    }

    // -------- store chunk partials --------
    {
        const int grow = b0 + wm * 32 + (lane >> 2);
        const int gcol = c0 + wn * 32 + (lane & 3) * 2;
        const size_t cbase = (size_t)ch * B_SZ * B_SZ;
#pragma unroll
        for (int mt = 0; mt < 2; ++mt)
#pragma unroll
            for (int nt = 0; nt < 4; ++nt) {
                const size_t i0 = cbase + (size_t)(grow + mt * 16) * B_SZ + (gcol + nt * 8);
                const size_t i1 = cbase + (size_t)(grow + mt * 16 + 8) * B_SZ + (gcol + nt * 8);
                *(float2*)&g_s[i0] = make_float2(sac[mt][nt][0], sac[mt][nt][1]);
                *(float2*)&g_s[i1] = make_float2(sac[mt][nt][2], sac[mt][nt][3]);
                *(float2*)&g_w[i0] = make_float2(wac[mt][nt][0], wac[mt][nt][1]);
                *(float2*)&g_w[i1] = make_float2(wac[mt][nt][2], wac[mt][nt][3]);
            }
    }
}

// ---------------- kernel 3: combine chunk partials -> logits ----------------
__global__ void __launch_bounds__(256) reduce_logits_kernel() {
    const int idx = blockIdx.x * 256 + threadIdx.x;   // < 262144
    float s = 0.f, w = 0.f;
#pragma unroll
    for (int chn = 0; chn < NCHUNK; ++chn) {
        s += g_s[(size_t)chn * (B_SZ * B_SZ) + idx];
        w += g_w[(size_t)chn * (B_SZ * B_SZ) + idx];
    }
    g_logits[idx] = (w / s) * (1.0f / 0.07f);
}

// ---------------- kernel 4: per-row & per-col LSE ----------------
__device__ __forceinline__ float block_reduce(float v, float* sm, bool do_max) {
#pragma unroll
    for (int o = 16; o; o >>= 1) {
        const float u = __shfl_xor_sync(0xffffffffu, v, o);
        v = do_max ? fmaxf(v, u) : (v + u);
    }
    if ((threadIdx.x & 31) == 0) sm[threadIdx.x >> 5] = v;
    __syncthreads();
    if (threadIdx.x < 32) {
        float u = (threadIdx.x < 16) ? sm[threadIdx.x] : (do_max ? -1e30f : 0.f);
#pragma unroll
        for (int o = 8; o; o >>= 1) {
            const float q = __shfl_xor_sync(0xffffffffu, u, o);
            u = do_max ? fmaxf(u, q) : (u + q);
        }
        if (threadIdx.x == 0) sm[16] = u;
    }
    __syncthreads();
    const float out = sm[16];
    __syncthreads();
    return out;
}

__global__ void __launch_bounds__(512) lse_kernel() {
    __shared__ float sm[32];
    const int b = blockIdx.x;
    const int i = threadIdx.x;
    const float rv = g_logits[b * B_SZ + i];
    const float cv = g_logits[i * B_SZ + b];
    const float rmax = block_reduce(rv, sm, true);
    const float cmax = block_reduce(cv, sm, true);
    const float rsum = block_reduce(__expf(rv - rmax), sm, false);
    const float csum = block_reduce(__expf(cv - cmax), sm, false);
    if (i == 0) {
        const float diag = g_logits[b * B_SZ + b];
        g_part[b] = (rmax + __logf(rsum)) + (cmax + __logf(csum)) - 2.0f * diag;
    }
}

// ---------------- kernel 5: final scalar ----------------
__global__ void __launch_bounds__(512) final_kernel(float* out) {
    __shared__ float sm[32];
    float v = g_part[threadIdx.x];
    const float s = block_reduce(v, sm, false);
    if (threadIdx.x == 0) out[0] = s * (1.0f / (2.0f * B_SZ));
}

// ---------------- launch ----------------
extern "C" void kernel_launch(void* const* d_in, const int* in_sizes, int n_in,
                              void* d_out, int out_size) {
    const float* text = (const float*)d_in[0];
    const float* vis  = (const float*)d_in[1];
    float* out = (float*)d_out;

    static bool attr_done = false;
    if (!attr_done) {
        cudaFuncSetAttribute(gemm_pool_kernel, cudaFuncAttributeMaxDynamicSharedMemorySize,
                             SMEM_TOTAL);
        attr_done = true;
    }

    // 2 * 512 * 196 rows, one warp per row, 8 warps per block
    convert_kernel<<<(2 * B_SZ * T_SZ) / 8, 256>>>(text, vis);
    gemm_pool_kernel<<<dim3(16, NCHUNK), 512, SMEM_TOTAL>>>();
    reduce_logits_kernel<<<(B_SZ * B_SZ) / 256, 256>>>();
    lse_kernel<<<B_SZ, 512>>>();
    final_kernel<<<1, 512>>>(out);
}

// round 6
// speedup vs baseline: 1.0692x; 1.0692x over previous
#include <cuda_runtime.h>
#include <cuda_bf16.h>
#include <cstdint>

// ---------------- problem constants ----------------
#define B_SZ 512
#define T_SZ 196
#define D_SZ 256
#define NCHUNK 9
#define TPC 22          // tokens per chunk (last chunk = 20)

// ---------------- device scratch ----------------
__device__ __align__(256) __nv_bfloat16 g_tbf[(size_t)T_SZ * B_SZ * D_SZ]; // [t][b][d], normalized
__device__ __align__(256) __nv_bfloat16 g_vbf[(size_t)T_SZ * B_SZ * D_SZ];
__device__ float g_s[(size_t)NCHUNK * B_SZ * B_SZ];   // partial sum exp(cos)
__device__ float g_w[(size_t)NCHUNK * B_SZ * B_SZ];   // partial sum cos*exp(cos)
__device__ float g_logits[B_SZ * B_SZ];
__device__ float g_logitsT[B_SZ * B_SZ];
__device__ float g_part[B_SZ];

// ---------------- PTX helpers (sm_80-class only; NO 'a'-gated features) ----------------
__device__ __forceinline__ uint32_t smem_u32(const void* p) {
    uint32_t a;
    asm("{ .reg .u64 t; cvta.to.shared.u64 t, %1; cvt.u32.u64 %0, t; }" : "=r"(a) : "l"(p));
    return a;
}
__device__ __forceinline__ void cp_async16(uint32_t dst, const void* src) {
    asm volatile("cp.async.cg.shared.global [%0], [%1], 16;" :: "r"(dst), "l"(src) : "memory");
}
__device__ __forceinline__ void cp_commit() {
    asm volatile("cp.async.commit_group;" ::: "memory");
}
template <int N>
__device__ __forceinline__ void cp_wait() {
    asm volatile("cp.async.wait_group %0;" :: "n"(N) : "memory");
}
__device__ __forceinline__ void ldsm_x4(uint32_t (&r)[4], uint32_t addr) {
    asm volatile("ldmatrix.sync.aligned.m8n8.x4.shared.b16 {%0,%1,%2,%3}, [%4];"
                 : "=r"(r[0]), "=r"(r[1]), "=r"(r[2]), "=r"(r[3]) : "r"(addr));
}
__device__ __forceinline__ void mma_16816(float (&d)[4], const uint32_t (&a)[4],
                                          uint32_t b0, uint32_t b1) {
    asm volatile(
        "mma.sync.aligned.m16n8k16.row.col.f32.bf16.bf16.f32 "
        "{%0,%1,%2,%3}, {%4,%5,%6,%7}, {%8,%9}, {%0,%1,%2,%3};"
        : "+f"(d[0]), "+f"(d[1]), "+f"(d[2]), "+f"(d[3])
        : "r"(a[0]), "r"(a[1]), "r"(a[2]), "r"(a[3]), "r"(b0), "r"(b1));
}

// ---------------- kernel 1: normalize + fp32->bf16 + transpose to [t][b][d] ----------------
__global__ void __launch_bounds__(256) convert_kernel(const float* __restrict__ text,
                                                      const float* __restrict__ vis) {
    const int gw = (blockIdx.x * blockDim.x + threadIdx.x) >> 5;
    const int lane = threadIdx.x & 31;
    const int ROWS = B_SZ * T_SZ;
    const int which = (gw >= ROWS) ? 1 : 0;
    const int r = gw - which * ROWS;
    const int b = r / T_SZ;
    const int t = r - b * T_SZ;

    const float4* src = (const float4*)((which ? vis : text) + ((size_t)b * T_SZ + t) * D_SZ);
    float4 x = src[lane];
    float4 y = src[lane + 32];
    float ss = x.x * x.x + x.y * x.y + x.z * x.z + x.w * x.w
             + y.x * y.x + y.y * y.y + y.z * y.z + y.w * y.w;
#pragma unroll
    for (int o = 16; o; o >>= 1) ss += __shfl_xor_sync(0xffffffffu, ss, o);
    const float rn = rsqrtf(ss);

    __nv_bfloat16* dst = (which ? g_vbf : g_tbf) + ((size_t)t * B_SZ + b) * D_SZ;
    __nv_bfloat162 h0 = __float22bfloat162_rn(make_float2(x.x * rn, x.y * rn));
    __nv_bfloat162 h1 = __float22bfloat162_rn(make_float2(x.z * rn, x.w * rn));
    __nv_bfloat162 h2 = __float22bfloat162_rn(make_float2(y.x * rn, y.y * rn));
    __nv_bfloat162 h3 = __float22bfloat162_rn(make_float2(y.z * rn, y.w * rn));
    uint2 p0, p1;
    p0.x = *(uint32_t*)&h0; p0.y = *(uint32_t*)&h1;
    p1.x = *(uint32_t*)&h2; p1.y = *(uint32_t*)&h3;
    ((uint2*)dst)[lane] = p0;
    ((uint2*)(dst + 128))[lane] = p1;
}

// ---------------- kernel 2: fused per-token GEMM + softmax-pool partials ----------------
// CTA tile: 128 (b) x 128 (c); K = 256 in 4 blocks of 64. 512 threads = 16 warps,
// each warp owns a 32x32 output tile. Classic multi-stage cp.async pipeline,
// ONE __syncthreads per stage.
static constexpr int STAGES = 5;
static constexpr int SLOT_BYTES = 32768;   // A 16KB + B 16KB (one K-block of 64)
static constexpr int A_HALF = 16384;
static constexpr int SMEM_TOTAL = STAGES * SLOT_BYTES;  // 163840

__global__ void __launch_bounds__(512, 1) gemm_pool_kernel() {
    extern __shared__ __align__(1024) char smem[];
    const uint32_t sb = smem_u32(smem);
    const int tid = threadIdx.x;
    const int wid = tid >> 5;
    const int lane = tid & 31;

    const int bx = blockIdx.x;
    const int ch = blockIdx.y;
    const int b0 = (bx & 3) * 128;
    const int c0 = (bx >> 2) * 128;
    const int t0 = ch * TPC;
    const int ntok = min(TPC, T_SZ - t0);
    const int NS = ntok * 4;

    // -------- per-thread producer addressing (4 x 16B chunks per thread per stage) --------
    uint32_t pdst[4];
    const __nv_bfloat16* psrcbase[4];
    uint32_t psrcrowoff[4];
#pragma unroll
    for (int i = 0; i < 4; ++i) {
        const int q = tid + i * 512;
        const int isB = q >> 10;
        const int q2 = q & 1023;
        const int row = q2 >> 3;
        const int c8 = q2 & 7;
        pdst[i] = (uint32_t)(isB ? A_HALF : 0) + (uint32_t)row * 128
                + ((uint32_t)(c8 ^ (row & 7)) << 4);
        psrcbase[i] = (isB ? g_vbf : g_tbf);
        psrcrowoff[i] = (uint32_t)((isB ? c0 : b0) + row) * D_SZ + (uint32_t)c8 * 8;
    }

    // -------- per-thread MMA fragment addressing --------
    const int wm = wid & 3;
    const int wn = wid >> 2;
    const uint32_t lx = lane & 7;
    const uint32_t aoff = (uint32_t)(wm * 32 + (lane & 15)) * 128;      // A row byte offset
    const uint32_t halfA = (uint32_t)(lane >> 4);
    const uint32_t boff = (uint32_t)(wn * 32 + (lane & 7) + ((lane >> 4) * 8)) * 128;
    const uint32_t halfB = (uint32_t)((lane >> 3) & 1);

    float acc[2][4][4];
    float sac[2][4][4];
    float wac[2][4][4];
#pragma unroll
    for (int mt = 0; mt < 2; ++mt)
#pragma unroll
        for (int nt = 0; nt < 4; ++nt)
#pragma unroll
            for (int r = 0; r < 4; ++r) {
                acc[mt][nt][r] = 0.f; sac[mt][nt][r] = 0.f; wac[mt][nt][r] = 0.f;
            }

    auto load_stage = [&](int s) {
        const int slot = s % STAGES;
        const int t = t0 + (s >> 2);
        const int kb = s & 3;
        const uint32_t sbase = sb + (uint32_t)slot * SLOT_BYTES;
        const size_t toff = (size_t)t * (B_SZ * D_SZ) + (size_t)kb * 64;
#pragma unroll
        for (int i = 0; i < 4; ++i)
            cp_async16(sbase + pdst[i], psrcbase[i] + toff + psrcrowoff[i]);
    };

#pragma unroll
    for (int s = 0; s < STAGES - 1; ++s) { load_stage(s); cp_commit(); }

    for (int s = 0; s < NS; ++s) {
        cp_wait<STAGES - 2>();
        __syncthreads();   // single sync per stage: slot (s-1) now safe to overwrite

        const int slot = s % STAGES;
        const uint32_t ab = sb + (uint32_t)slot * SLOT_BYTES;
        const uint32_t bb = ab + A_HALF;
#pragma unroll
        for (int ks = 0; ks < 4; ++ks) {
            const uint32_t ca = (((uint32_t)(ks << 1) | halfA) ^ lx) << 4;
            const uint32_t cb = (((uint32_t)(ks << 1) | halfB) ^ lx) << 4;
            uint32_t a0[4], a1[4], bA[4], bB[4];
            ldsm_x4(a0, ab + aoff + ca);
            ldsm_x4(a1, ab + aoff + 2048 + ca);
            ldsm_x4(bA, bb + boff + cb);
            ldsm_x4(bB, bb + boff + 2048 + cb);
            mma_16816(acc[0][0], a0, bA[0], bA[1]);
            mma_16816(acc[0][1], a0, bA[2], bA[3]);
            mma_16816(acc[0][2], a0, bB[0], bB[1]);
            mma_16816(acc[0][3], a0, bB[2], bB[3]);
            mma_16816(acc[1][0], a1, bA[0], bA[1]);
            mma_16816(acc[1][1], a1, bA[2], bA[3]);
            mma_16816(acc[1][2], a1, bB[0], bB[1]);
            mma_16816(acc[1][3], a1, bB[2], bB[3]);
        }

        // issue next stage's loads before the epilogue math
        if (s + STAGES - 1 < NS) load_stage(s + STAGES - 1);
        cp_commit();

        if ((s & 3) == 3) {
            // end of a token: fold cos values into softmax-pool partials.
            // __expf -> MUFU pipe; keeps the FMA pipe mostly free for MMA addressing.
#pragma unroll
            for (int mt = 0; mt < 2; ++mt)
#pragma unroll
                for (int nt = 0; nt < 4; ++nt)
#pragma unroll
                    for (int r = 0; r < 4; ++r) {
                        const float c = acc[mt][nt][r];
                        const float e = __expf(c);
                        sac[mt][nt][r] += e;
                        wac[mt][nt][r] = fmaf(c, e, wac[mt][nt][r]);
                        acc[mt][nt][r] = 0.f;
                    }
        }
    }

    // -------- store chunk partials --------
    {
        const int grow = b0 + wm * 32 + (lane >> 2);
        const int gcol = c0 + wn * 32 + (lane & 3) * 2;
        const size_t cbase = (size_t)ch * B_SZ * B_SZ;
#pragma unroll
        for (int mt = 0; mt < 2; ++mt)
#pragma unroll
            for (int nt = 0; nt < 4; ++nt) {
                const size_t i0 = cbase + (size_t)(grow + mt * 16) * B_SZ + (gcol + nt * 8);
                const size_t i1 = cbase + (size_t)(grow + mt * 16 + 8) * B_SZ + (gcol + nt * 8);
                *(float2*)&g_s[i0] = make_float2(sac[mt][nt][0], sac[mt][nt][1]);
                *(float2*)&g_s[i1] = make_float2(sac[mt][nt][2], sac[mt][nt][3]);
                *(float2*)&g_w[i0] = make_float2(wac[mt][nt][0], wac[mt][nt][1]);
                *(float2*)&g_w[i1] = make_float2(wac[mt][nt][2], wac[mt][nt][3]);
            }
    }
}

// ---------------- kernel 3: combine chunk partials -> logits (+ transposed copy) ----------------
__global__ void __launch_bounds__(256) reduce_logits_kernel() {
    __shared__ float tile[32][33];
    const int tx = threadIdx.x & 31;
    const int ty = threadIdx.x >> 5;         // 0..7
    const int r0 = blockIdx.y * 32;
    const int c0 = blockIdx.x * 32;
#pragma unroll
    for (int j = 0; j < 4; ++j) {
        const int r = ty + j * 8;
        const int idx = (r0 + r) * B_SZ + c0 + tx;
        float s = 0.f, w = 0.f;
#pragma unroll
        for (int chn = 0; chn < NCHUNK; ++chn) {
            s += g_s[(size_t)chn * (B_SZ * B_SZ) + idx];
            w += g_w[(size_t)chn * (B_SZ * B_SZ) + idx];
        }
        const float v = (w / s) * (1.0f / 0.07f);
        g_logits[idx] = v;
        tile[r][tx] = v;
    }
    __syncthreads();
#pragma unroll
    for (int j = 0; j < 4; ++j) {
        const int r = ty + j * 8;
        g_logitsT[(size_t)(c0 + r) * B_SZ + r0 + tx] = tile[tx][r];
    }
}

// ---------------- kernel 4: per-row & per-col LSE ----------------
__device__ __forceinline__ float block_reduce(float v, float* sm, bool do_max) {
#pragma unroll
    for (int o = 16; o; o >>= 1) {
        const float u = __shfl_xor_sync(0xffffffffu, v, o);
        v = do_max ? fmaxf(v, u) : (v + u);
    }
    if ((threadIdx.x & 31) == 0) sm[threadIdx.x >> 5] = v;
    __syncthreads();
    if (threadIdx.x < 32) {
        float u = (threadIdx.x < 16) ? sm[threadIdx.x] : (do_max ? -1e30f : 0.f);
#pragma unroll
        for (int o = 8; o; o >>= 1) {
            const float q = __shfl_xor_sync(0xffffffffu, u, o);
            u = do_max ? fmaxf(u, q) : (u + q);
        }
        if (threadIdx.x == 0) sm[16] = u;
    }
    __syncthreads();
    const float out = sm[16];
    __syncthreads();
    return out;
}

__global__ void __launch_bounds__(512) lse_kernel() {
    __shared__ float sm[32];
    const int b = blockIdx.x;
    const int i = threadIdx.x;
    const float rv = g_logits[b * B_SZ + i];
    const float cv = g_logitsT[b * B_SZ + i];   // column b, coalesced
    const float rmax = block_reduce(rv, sm, true);
    const float cmax = block_reduce(cv, sm, true);
    const float rsum = block_reduce(__expf(rv - rmax), sm, false);
    const float csum = block_reduce(__expf(cv - cmax), sm, false);
    if (i == 0) {
        const float diag = g_logits[b * B_SZ + b];
        g_part[b] = (rmax + __logf(rsum)) + (cmax + __logf(csum)) - 2.0f * diag;
    }
}

// ---------------- kernel 5: final scalar ----------------
__global__ void __launch_bounds__(512) final_kernel(float* out) {
    __shared__ float sm[32];
    float v = g_part[threadIdx.x];
    const float s = block_reduce(v, sm, false);
    if (threadIdx.x == 0) out[0] = s * (1.0f / (2.0f * B_SZ));
}

// ---------------- launch ----------------
extern "C" void kernel_launch(void* const* d_in, const int* in_sizes, int n_in,
                              void* d_out, int out_size) {
    const float* text = (const float*)d_in[0];
    const float* vis  = (const float*)d_in[1];
    float* out = (float*)d_out;

    static bool attr_done = false;
    if (!attr_done) {
        cudaFuncSetAttribute(gemm_pool_kernel, cudaFuncAttributeMaxDynamicSharedMemorySize,
                             SMEM_TOTAL);
        attr_done = true;
    }

    convert_kernel<<<(2 * B_SZ * T_SZ) / 8, 256>>>(text, vis);
    gemm_pool_kernel<<<dim3(16, NCHUNK), 512, SMEM_TOTAL>>>();
    reduce_logits_kernel<<<dim3(16, 16), 256>>>();
    lse_kernel<<<B_SZ, 512>>>();
    final_kernel<<<1, 512>>>(out);
}

// round 7
// speedup vs baseline: 1.1288x; 1.0558x over previous
#include <cuda_runtime.h>
#include <cuda_bf16.h>
#include <cstdint>

// ---------------- problem constants ----------------
#define B_SZ 512
#define T_SZ 196
#define D_SZ 256
#define NCHUNK 9
#define TPC 22          // tokens per chunk (last chunk = 20)

// ---------------- device scratch ----------------
__device__ __align__(256) __nv_bfloat16 g_tbf[(size_t)T_SZ * B_SZ * D_SZ]; // [t][b][d], normalized
__device__ __align__(256) __nv_bfloat16 g_vbf[(size_t)T_SZ * B_SZ * D_SZ];
__device__ float g_s[(size_t)NCHUNK * B_SZ * B_SZ];   // partial sum exp(cos)
__device__ float g_w[(size_t)NCHUNK * B_SZ * B_SZ];   // partial sum cos*exp(cos)
__device__ float g_logits[B_SZ * B_SZ];
__device__ float g_logitsT[B_SZ * B_SZ];
__device__ float g_part[B_SZ];

// ---------------- PTX helpers (sm_80-class only; NO 'a'-gated features) ----------------
__device__ __forceinline__ uint32_t smem_u32(const void* p) {
    uint32_t a;
    asm("{ .reg .u64 t; cvta.to.shared.u64 t, %1; cvt.u32.u64 %0, t; }" : "=r"(a) : "l"(p));
    return a;
}
__device__ __forceinline__ void cp_async16(uint32_t dst, const void* src) {
    asm volatile("cp.async.cg.shared.global [%0], [%1], 16;" :: "r"(dst), "l"(src) : "memory");
}
__device__ __forceinline__ void cp_commit() {
    asm volatile("cp.async.commit_group;" ::: "memory");
}
template <int N>
__device__ __forceinline__ void cp_wait() {
    asm volatile("cp.async.wait_group %0;" :: "n"(N) : "memory");
}
__device__ __forceinline__ void ldsm_x4(uint32_t (&r)[4], uint32_t addr) {
    asm volatile("ldmatrix.sync.aligned.m8n8.x4.shared.b16 {%0,%1,%2,%3}, [%4];"
                 : "=r"(r[0]), "=r"(r[1]), "=r"(r[2]), "=r"(r[3]) : "r"(addr));
}
__device__ __forceinline__ void mma_16816(float (&d)[4], const uint32_t (&a)[4],
                                          uint32_t b0, uint32_t b1) {
    asm volatile(
        "mma.sync.aligned.m16n8k16.row.col.f32.bf16.bf16.f32 "
        "{%0,%1,%2,%3}, {%4,%5,%6,%7}, {%8,%9}, {%0,%1,%2,%3};"
        : "+f"(d[0]), "+f"(d[1]), "+f"(d[2]), "+f"(d[3])
        : "r"(a[0]), "r"(a[1]), "r"(a[2]), "r"(a[3]), "r"(b0), "r"(b1));
}

// ---------------- dummy kernel (shifts ncu launch-slot so gemm may get profiled) ----------------
__global__ void dummy_kernel() {}

// ---------------- kernel 1: normalize + fp32->bf16 + transpose to [t][b][d] ----------------
__global__ void __launch_bounds__(256) convert_kernel(const float* __restrict__ text,
                                                      const float* __restrict__ vis) {
    const int gw = (blockIdx.x * blockDim.x + threadIdx.x) >> 5;
    const int lane = threadIdx.x & 31;
    const int ROWS = B_SZ * T_SZ;
    const int which = (gw >= ROWS) ? 1 : 0;
    const int r = gw - which * ROWS;
    const int b = r / T_SZ;
    const int t = r - b * T_SZ;

    const float4* src = (const float4*)((which ? vis : text) + ((size_t)b * T_SZ + t) * D_SZ);
    float4 x = src[lane];
    float4 y = src[lane + 32];
    float ss = x.x * x.x + x.y * x.y + x.z * x.z + x.w * x.w
             + y.x * y.x + y.y * y.y + y.z * y.z + y.w * y.w;
#pragma unroll
    for (int o = 16; o; o >>= 1) ss += __shfl_xor_sync(0xffffffffu, ss, o);
    const float rn = rsqrtf(ss);

    __nv_bfloat16* dst = (which ? g_vbf : g_tbf) + ((size_t)t * B_SZ + b) * D_SZ;
    __nv_bfloat162 h0 = __float22bfloat162_rn(make_float2(x.x * rn, x.y * rn));
    __nv_bfloat162 h1 = __float22bfloat162_rn(make_float2(x.z * rn, x.w * rn));
    __nv_bfloat162 h2 = __float22bfloat162_rn(make_float2(y.x * rn, y.y * rn));
    __nv_bfloat162 h3 = __float22bfloat162_rn(make_float2(y.z * rn, y.w * rn));
    uint2 p0, p1;
    p0.x = *(uint32_t*)&h0; p0.y = *(uint32_t*)&h1;
    p1.x = *(uint32_t*)&h2; p1.y = *(uint32_t*)&h3;
    ((uint2*)dst)[lane] = p0;
    ((uint2*)(dst + 128))[lane] = p1;
}

// ---------------- kernel 2: fused per-token GEMM + softmax-pool partials ----------------
// CTA tile: 128 (b) x 128 (c). Stage = K-half of 128 (two K64 sub-blocks), 64KB per slot,
// 3-slot ring (192KB). 512 threads = 16 warps, each owns a 32x32 output tile.
// Loads for stage s+2 issued right after the stage-s sync (WAR-safe), before compute.
static constexpr int STAGES = 3;
static constexpr int SLOT_BYTES = 65536;    // [A0 16K][B0 16K][A1 16K][B1 16K]
static constexpr int SMEM_TOTAL = STAGES * SLOT_BYTES;  // 196608

__global__ void __launch_bounds__(512, 1) gemm_pool_kernel() {
    extern __shared__ __align__(1024) char smem[];
    const uint32_t sb = smem_u32(smem);
    const int tid = threadIdx.x;
    const int wid = tid >> 5;
    const int lane = tid & 31;

    const int bx = blockIdx.x;
    const int ch = blockIdx.y;
    const int b0 = (bx & 3) * 128;
    const int c0 = (bx >> 2) * 128;
    const int t0 = ch * TPC;
    const int ntok = min(TPC, T_SZ - t0);
    const int NS2 = ntok * 2;   // stages (K128 each)

    // -------- producer addressing (8 x 16B chunks / thread / stage) --------
    // chunk i: q=(i<<9)|tid; kb2=i>>2, isB=(i>>1)&1, row=(tid>>3)+((i&1)<<6), c8=tid&7
    // dst  = i*8192 + (tid>>3)*128 + ((c8 ^ ((tid>>3)&7))<<4)
    // src  = base(isB) + (i&1)*16384 + (i>>2)*64  [+ stage: t*131072 + kh*128]
    const uint32_t pbase = (uint32_t)(tid >> 3) * 128
                         + (uint32_t)(((tid & 7) ^ ((tid >> 3) & 7)) << 4);
    const __nv_bfloat16* pa = g_tbf + (size_t)b0 * 256 + (tid >> 3) * 256 + (tid & 7) * 8;
    const __nv_bfloat16* pb = g_vbf + (size_t)c0 * 256 + (tid >> 3) * 256 + (tid & 7) * 8;

    // -------- per-thread MMA fragment addressing (within 16KB sub-blocks) --------
    const int wm = wid & 3;
    const int wn = wid >> 2;
    const uint32_t lx = lane & 7;
    const uint32_t aoff = (uint32_t)(wm * 32 + (lane & 15)) * 128;
    const uint32_t halfA = (uint32_t)(lane >> 4);
    const uint32_t boff = (uint32_t)(wn * 32 + (lane & 7) + ((lane >> 4) * 8)) * 128;
    const uint32_t halfB = (uint32_t)((lane >> 3) & 1);

    float acc[2][4][4];
    float sac[2][4][4];
    float wac[2][4][4];
#pragma unroll
    for (int mt = 0; mt < 2; ++mt)
#pragma unroll
        for (int nt = 0; nt < 4; ++nt)
#pragma unroll
            for (int r = 0; r < 4; ++r) {
                acc[mt][nt][r] = 0.f; sac[mt][nt][r] = 0.f; wac[mt][nt][r] = 0.f;
            }

    auto load_stage = [&](int s) {
        const int slot = s % STAGES;
        const size_t toff = (size_t)(t0 + (s >> 1)) * (B_SZ * D_SZ) + (size_t)(s & 1) * 128;
        const uint32_t sbase = sb + (uint32_t)slot * SLOT_BYTES + pbase;
#pragma unroll
        for (int i = 0; i < 8; ++i) {
            const __nv_bfloat16* src = ((i >> 1) & 1 ? pb : pa) + toff
                                     + (i & 1) * 16384 + (i >> 2) * 64;
            cp_async16(sbase + (uint32_t)i * 8192, src);
        }
    };

    load_stage(0); cp_commit();
    load_stage(1); cp_commit();

    for (int s = 0; s < NS2; ++s) {
        cp_wait<1>();
        __syncthreads();

        // issue next stage's loads first (slot (s+2)%3 was consumed at stage s-1)
        if (s + 2 < NS2) load_stage(s + 2);
        cp_commit();

        const uint32_t base = sb + (uint32_t)(s % STAGES) * SLOT_BYTES;
#pragma unroll
        for (int kb2 = 0; kb2 < 2; ++kb2) {
            const uint32_t ab = base + (uint32_t)kb2 * 32768;
            const uint32_t bb = ab + 16384;
#pragma unroll
            for (int ks = 0; ks < 4; ++ks) {
                const uint32_t ca = (((uint32_t)(ks << 1) | halfA) ^ lx) << 4;
                const uint32_t cb = (((uint32_t)(ks << 1) | halfB) ^ lx) << 4;
                uint32_t a0[4], a1[4], bA[4], bB[4];
                ldsm_x4(a0, ab + aoff + ca);
                ldsm_x4(a1, ab + aoff + 2048 + ca);
                ldsm_x4(bA, bb + boff + cb);
                ldsm_x4(bB, bb + boff + 2048 + cb);
                mma_16816(acc[0][0], a0, bA[0], bA[1]);
                mma_16816(acc[0][1], a0, bA[2], bA[3]);
                mma_16816(acc[0][2], a0, bB[0], bB[1]);
                mma_16816(acc[0][3], a0, bB[2], bB[3]);
                mma_16816(acc[1][0], a1, bA[0], bA[1]);
                mma_16816(acc[1][1], a1, bA[2], bA[3]);
                mma_16816(acc[1][2], a1, bB[0], bB[1]);
                mma_16816(acc[1][3], a1, bB[2], bB[3]);
            }
        }

        if (s & 1) {
            // end of a token: fold cos into softmax-pool partials (MUFU exp)
#pragma unroll
            for (int mt = 0; mt < 2; ++mt)
#pragma unroll
                for (int nt = 0; nt < 4; ++nt)
#pragma unroll
                    for (int r = 0; r < 4; ++r) {
                        const float c = acc[mt][nt][r];
                        const float e = __expf(c);
                        sac[mt][nt][r] += e;
                        wac[mt][nt][r] = fmaf(c, e, wac[mt][nt][r]);
                        acc[mt][nt][r] = 0.f;
                    }
        }
    }

    // -------- store chunk partials --------
    {
        const int grow = b0 + wm * 32 + (lane >> 2);
        const int gcol = c0 + wn * 32 + (lane & 3) * 2;
        const size_t cbase = (size_t)ch * B_SZ * B_SZ;
#pragma unroll
        for (int mt = 0; mt < 2; ++mt)
#pragma unroll
            for (int nt = 0; nt < 4; ++nt) {
                const size_t i0 = cbase + (size_t)(grow + mt * 16) * B_SZ + (gcol + nt * 8);
                const size_t i1 = cbase + (size_t)(grow + mt * 16 + 8) * B_SZ + (gcol + nt * 8);
                *(float2*)&g_s[i0] = make_float2(sac[mt][nt][0], sac[mt][nt][1]);
                *(float2*)&g_s[i1] = make_float2(sac[mt][nt][2], sac[mt][nt][3]);
                *(float2*)&g_w[i0] = make_float2(wac[mt][nt][0], wac[mt][nt][1]);
                *(float2*)&g_w[i1] = make_float2(wac[mt][nt][2], wac[mt][nt][3]);
            }
    }
}

// ---------------- kernel 3: combine chunk partials -> logits (+ transposed copy) ----------------
__global__ void __launch_bounds__(256) reduce_logits_kernel() {
    __shared__ float tile[32][33];
    const int tx = threadIdx.x & 31;
    const int ty = threadIdx.x >> 5;         // 0..7
    const int r0 = blockIdx.y * 32;
    const int c0 = blockIdx.x * 32;
#pragma unroll
    for (int j = 0; j < 4; ++j) {
        const int r = ty + j * 8;
        const int idx = (r0 + r) * B_SZ + c0 + tx;
        float s = 0.f, w = 0.f;
#pragma unroll
        for (int chn = 0; chn < NCHUNK; ++chn) {
            s += g_s[(size_t)chn * (B_SZ * B_SZ) + idx];
            w += g_w[(size_t)chn * (B_SZ * B_SZ) + idx];
        }
        const float v = (w / s) * (1.0f / 0.07f);
        g_logits[idx] = v;
        tile[r][tx] = v;
    }
    __syncthreads();
#pragma unroll
    for (int j = 0; j < 4; ++j) {
        const int r = ty + j * 8;
        g_logitsT[(size_t)(c0 + r) * B_SZ + r0 + tx] = tile[tx][r];
    }
}

// ---------------- kernel 4: per-row & per-col LSE ----------------
// logits in [-14.4, 14.4] (cos in [-1,1]/0.07): exp is fp32-safe -> no max pass.
__device__ __forceinline__ float block_sum(float v, float* sm) {
#pragma unroll
    for (int o = 16; o; o >>= 1) v += __shfl_xor_sync(0xffffffffu, v, o);
    if ((threadIdx.x & 31) == 0) sm[threadIdx.x >> 5] = v;
    __syncthreads();
    if (threadIdx.x < 32) {
        float u = (threadIdx.x < 16) ? sm[threadIdx.x] : 0.f;
#pragma unroll
        for (int o = 8; o; o >>= 1) u += __shfl_xor_sync(0xffffffffu, u, o);
        if (threadIdx.x == 0) sm[16] = u;
    }
    __syncthreads();
    const float out = sm[16];
    __syncthreads();
    return out;
}

__global__ void __launch_bounds__(512) lse_kernel() {
    __shared__ float sm[32];
    const int b = blockIdx.x;
    const int i = threadIdx.x;
    const float rv = g_logits[b * B_SZ + i];
    const float cv = g_logitsT[b * B_SZ + i];   // column b, coalesced
    const float rsum = block_sum(__expf(rv), sm);
    const float csum = block_sum(__expf(cv), sm);
    if (i == 0) {
        const float diag = g_logits[b * B_SZ + b];
        g_part[b] = __logf(rsum) + __logf(csum) - 2.0f * diag;
    }
}

// ---------------- kernel 5: final scalar ----------------
__global__ void __launch_bounds__(512) final_kernel(float* out) {
    __shared__ float sm[32];
    float v = g_part[threadIdx.x];
    const float s = block_sum(v, sm);
    if (threadIdx.x == 0) out[0] = s * (1.0f / (2.0f * B_SZ));
}

// ---------------- launch ----------------
extern "C" void kernel_launch(void* const* d_in, const int* in_sizes, int n_in,
                              void* d_out, int out_size) {
    const float* text = (const float*)d_in[0];
    const float* vis  = (const float*)d_in[1];
    float* out = (float*)d_out;

    static bool attr_done = false;
    if (!attr_done) {
        cudaFuncSetAttribute(gemm_pool_kernel, cudaFuncAttributeMaxDynamicSharedMemorySize,
                             SMEM_TOTAL);
        attr_done = true;
    }

    dummy_kernel<<<1, 32>>>();
    convert_kernel<<<(2 * B_SZ * T_SZ) / 8, 256>>>(text, vis);
    gemm_pool_kernel<<<dim3(16, NCHUNK), 512, SMEM_TOTAL>>>();
    reduce_logits_kernel<<<dim3(16, 16), 256>>>();
    lse_kernel<<<B_SZ, 512>>>();
    final_kernel<<<1, 512>>>(out);
}